// round 15
// baseline (speedup 1.0000x reference)
#include <cuda_runtime.h>
#include <cuda_fp16.h>
#include <cstdint>

#define SEQ   256
#define NB    64
#define INP   1024
#define HID   1024
#define SBH   (SEQ*NB*HID)
#define NCTA  128        // recurrence CTAs (barrier population)
#define NHELP 20         // helper CTAs
#define TSIN  160        // steps with inline x; [TSIN,SEQ) precomputed by helpers
#define GST   33
#define GSZ   (64*GST)
#define WTILE 16384

// ---- device scratch ----
__device__ uint32_t g_xv[(size_t)SEQ*NB*HID/2];  // x*mask_x, fp16x2, A-frag layout
__device__ uint32_t g_hm[2][NB*HID/2];           // masked h, fp16x2, A-frag layout
__device__ uint32_t g_wt[(size_t)2*NCTA*WTILE];  // [0]=W_hh, [1]=W_ih tiles (B-frag)
__device__ __half   g_xgh[(size_t)SEQ*NB*HID*4]; // xg fp16 [t][b][u][g] (tail only)
__device__ int      g_bar[SEQ];
__device__ int      g_xfl[SEQ];                  // helper completion counters (target 64)

__device__ __forceinline__ void mma16h(float* d, const uint32_t* a, const uint32_t* b) {
    asm volatile(
        "mma.sync.aligned.m16n8k16.row.col.f32.f16.f16.f32 "
        "{%0,%1,%2,%3},{%4,%5,%6,%7},{%8,%9},{%0,%1,%2,%3};\n"
        : "+f"(d[0]), "+f"(d[1]), "+f"(d[2]), "+f"(d[3])
        : "r"(a[0]), "r"(a[1]), "r"(a[2]), "r"(a[3]), "r"(b[0]), "r"(b[1]));
}
__device__ __forceinline__ float sigf(float x)  { return 1.f/(1.f+__expf(-x)); }
__device__ __forceinline__ float tanh_f(float x){ return 2.f/(1.f+__expf(-2.f*x)) - 1.f; }
__device__ __forceinline__ void bar_red_release(int* p) {
    asm volatile("red.release.gpu.global.add.s32 [%0], 1;" :: "l"(p) : "memory");
}
__device__ __forceinline__ int bar_ld_acquire(int* p) {
    int v;
    asm volatile("ld.acquire.gpu.global.b32 %0, [%1];" : "=r"(v) : "l"(p) : "memory");
    return v;
}
__device__ __forceinline__ uint32_t packh2(float lo, float hi) {
    __half2 h = __floats2half2_rn(lo, hi);
    return *reinterpret_cast<uint32_t*>(&h);
}
__device__ __forceinline__ int hp_addr(int b, int pk) {   // proven A-frag layout
    int mt = b >> 4, rb = b & 15;
    int c  = pk >> 3, pkl = pk & 7;
    int lane = (rb & 7)*4 + (pkl & 3);
    int e    = (pkl >> 2)*2 + (rb >> 3);
    return (mt*64 + c)*128 + lane*4 + e;
}

// ---- x*mask_x -> fp16x2 A-frag layout (proven) ----
__global__ void k_xprep(const float* __restrict__ x, const float* __restrict__ mx) {
    int i = blockIdx.x*256 + threadIdx.x;
    int t = i >> 15;
    int d = i & 32767;
    int b = d >> 9, pk = d & 511;
    int u0 = pk*2;
    const float* xs = x  + ((size_t)t*NB + b)*INP + u0;
    const float* ms = mx + (size_t)b*INP + u0;
    g_xv[(size_t)t*32768 + hp_addr(b, pk)] = packh2(xs[0]*ms[0], xs[1]*ms[1]);
}

// ---- init (proven) + zero xfl ----
__global__ void k_setup(const float* __restrict__ h0, const float* __restrict__ mh) {
    int i = blockIdx.x*256 + threadIdx.x;
    int b = i >> 9, pk = i & 511;
    int u0 = pk*2;
    int s = b*HID + u0;
    g_hm[0][hp_addr(b, pk)] = packh2(h0[s]*mh[s], h0[s+1]*mh[s+1]);
    if (blockIdx.x == 0) { g_bar[threadIdx.x] = 0; g_xfl[threadIdx.x] = 0; }
}

// ---- W prep (proven) ----
__global__ void k_wprep(const float* __restrict__ W, int which) {
    int gi = blockIdx.x*256 + threadIdx.x;
    int cb = gi >> 14;
    int d  = gi & 16383;
    int blk = d >> 7;
    int lane_e = d & 127;
    int chunk = blk >> 1, ntp = blk & 1;
    int lane = lane_e >> 2, e = lane_e & 3;
    int lq = lane >> 2, q4 = lane & 3;
    int nt = ntp*2 + (e >> 1);
    int pk_off = q4 + (e & 1)*4;
    int n = nt*8 + lq;
    int g = n >> 3, j = n & 7;
    const float* src = W + ((size_t)(g*HID + cb*8 + j))*HID + (chunk*8 + pk_off)*2;
    g_wt[(size_t)which*NCTA*WTILE + gi] = packh2(src[0], src[1]);
}

// per-warp GEMM pass over K=512 (proven R9)
#define MMA_PASS(ABASE, W4) do {                                               \
    const uint4* ap0 = (ABASE) + whalf*2*2048 + wkq*1024 + lane;               \
    const uint4* ap1 = ap0 + 2048;                                             \
    uint4 afr[8][2];                                                           \
    _Pragma("unroll")                                                          \
    for (int s = 0; s < 8; s++) {                                              \
        afr[s][0] = __ldcg(ap0 + s*32);                                        \
        afr[s][1] = __ldcg(ap1 + s*32);                                        \
    }                                                                          \
    _Pragma("unroll")                                                          \
    for (int g8 = 0; g8 < 4; g8++) {                                           \
        _Pragma("unroll")                                                      \
        for (int s = 0; s < 8; s++) {                                          \
            const int cq = g8*8 + s;                                           \
            uint4 A0 = afr[s][0], A1 = afr[s][1];                              \
            if (g8 < 3) {                                                      \
                afr[s][0] = __ldcg(ap0 + (cq+8)*32);                           \
                afr[s][1] = __ldcg(ap1 + (cq+8)*32);                           \
            }                                                                  \
            const int bidx = (wkq*32 + cq)*64 + lane;                          \
            uint4 b01 = (W4)[bidx];                                            \
            uint4 b23 = (W4)[bidx + 32];                                       \
            uint32_t af0[4] = {A0.x, A0.y, A0.z, A0.w};                        \
            uint32_t af1[4] = {A1.x, A1.y, A1.z, A1.w};                        \
            uint32_t bf0[2] = {b01.x, b01.y};                                  \
            uint32_t bf1[2] = {b01.z, b01.w};                                  \
            uint32_t bf2[2] = {b23.x, b23.y};                                  \
            uint32_t bf3[2] = {b23.z, b23.w};                                  \
            mma16h(acc[0][0], af0, bf0); mma16h(acc[1][0], af1, bf0);          \
            mma16h(acc[0][1], af0, bf1); mma16h(acc[1][1], af1, bf1);          \
            mma16h(acc[0][2], af0, bf2); mma16h(acc[1][2], af1, bf2);          \
            mma16h(acc[0][3], af0, bf3); mma16h(acc[1][3], af1, bf3);          \
        }                                                                      \
    }                                                                          \
} while (0)

#define STORE_GATES(RG) do {                                                   \
    float* gp = gsm + (RG)*GSZ;                                                \
    const int lq = lane >> 2, q4 = lane & 3;                                   \
    _Pragma("unroll")                                                          \
    for (int mt = 0; mt < 2; mt++) {                                           \
        const int r0 = whalf*32 + mt*16 + lq;                                  \
        _Pragma("unroll")                                                      \
        for (int nt = 0; nt < 4; nt++) {                                       \
            const int c = nt*8 + q4*2;                                         \
            gp[r0*GST + c]       = acc[mt][nt][0];                             \
            gp[r0*GST + c + 1]   = acc[mt][nt][1];                             \
            gp[(r0+8)*GST + c]   = acc[mt][nt][2];                             \
            gp[(r0+8)*GST + c+1] = acc[mt][nt][3];                             \
        }                                                                      \
    }                                                                          \
} while (0)

// helper xg micro-step (proven R10)
#define XGMMA(AV, BV) do {                                                     \
    _Pragma("unroll")                                                          \
    for (int mt = 0; mt < 4; mt++) {                                           \
        uint32_t af[4] = {(AV)[mt].x, (AV)[mt].y, (AV)[mt].z, (AV)[mt].w};     \
        uint32_t bf0[2] = {(BV)[0].x, (BV)[0].y};                              \
        uint32_t bf1[2] = {(BV)[0].z, (BV)[0].w};                              \
        uint32_t bf2[2] = {(BV)[1].x, (BV)[1].y};                              \
        uint32_t bf3[2] = {(BV)[1].z, (BV)[1].w};                              \
        uint32_t bf4[2] = {(BV)[2].x, (BV)[2].y};                              \
        uint32_t bf5[2] = {(BV)[2].z, (BV)[2].w};                              \
        uint32_t bf6[2] = {(BV)[3].x, (BV)[3].y};                              \
        uint32_t bf7[2] = {(BV)[3].z, (BV)[3].w};                              \
        mma16h(xac[mt][0], af, bf0); mma16h(xac[mt][1], af, bf1);              \
        mma16h(xac[mt][2], af, bf2); mma16h(xac[mt][3], af, bf3);              \
        mma16h(xac[mt][4], af, bf4); mma16h(xac[mt][5], af, bf5);              \
        mma16h(xac[mt][6], af, bf6); mma16h(xac[mt][7], af, bf7);              \
    }                                                                          \
} while (0)

// ---- single persistent kernel: 128 recurrence CTAs + 20 helper CTAs ----
__global__ void __launch_bounds__(256, 1) k_main(const float* __restrict__ c0,
                                                 const float* __restrict__ mh,
                                                 const float* __restrict__ b_ih,
                                                 const float* __restrict__ b_hh,
                                                 float* __restrict__ out) {
    const int tid  = threadIdx.x;
    const int lane = tid & 31;
    const int w    = tid >> 5;

    if (blockIdx.x >= NCTA) {
        // ================= HELPER: xg for t in [TSIN, SEQ) (R10-proven body) ===========
        const int hw = (blockIdx.x - NCTA)*8 + w;          // helper warp id 0..159
        const int lq = lane >> 2, q4 = lane & 3;
        const int total = (SEQ - TSIN)*64;
        for (int idx = hw; idx < total; idx += NHELP*8) {
            const int t   = TSIN + (idx >> 6);
            const int cbb = (idx & 63)*2;
            const uint4* ap  = reinterpret_cast<const uint4*>(g_xv) + (size_t)t*8192 + lane;
            const uint4* bt0 = reinterpret_cast<const uint4*>(g_wt + ((size_t)NCTA + cbb)*WTILE) + lane;
            const uint4* bt1 = reinterpret_cast<const uint4*>(g_wt + ((size_t)NCTA + cbb + 1)*WTILE) + lane;

            float xac[4][8][4];
            #pragma unroll
            for (int mt = 0; mt < 4; mt++)
                #pragma unroll
                for (int nt = 0; nt < 8; nt++)
                    #pragma unroll
                    for (int e = 0; e < 4; e++) xac[mt][nt][e] = 0.f;

            uint4 ab[2][4], bb[2][4];
            #pragma unroll
            for (int s = 0; s < 2; s++) {
                #pragma unroll
                for (int mt = 0; mt < 4; mt++) ab[s][mt] = __ldcg(ap + mt*2048 + s*32);
                bb[s][0] = __ldcg(bt0 + s*64);  bb[s][1] = __ldcg(bt0 + s*64 + 32);
                bb[s][2] = __ldcg(bt1 + s*64);  bb[s][3] = __ldcg(bt1 + s*64 + 32);
            }
            #pragma unroll 1
            for (int c2 = 0; c2 < 32; ++c2) {
                const int c0i = c2*2;
                {
                    uint4 A[4] = {ab[0][0], ab[0][1], ab[0][2], ab[0][3]};
                    uint4 B[4] = {bb[0][0], bb[0][1], bb[0][2], bb[0][3]};
                    if (c0i + 2 < 64) {
                        #pragma unroll
                        for (int mt = 0; mt < 4; mt++) ab[0][mt] = __ldcg(ap + mt*2048 + (c0i+2)*32);
                        bb[0][0] = __ldcg(bt0 + (c0i+2)*64);  bb[0][1] = __ldcg(bt0 + (c0i+2)*64 + 32);
                        bb[0][2] = __ldcg(bt1 + (c0i+2)*64);  bb[0][3] = __ldcg(bt1 + (c0i+2)*64 + 32);
                    }
                    XGMMA(A, B);
                }
                {
                    uint4 A[4] = {ab[1][0], ab[1][1], ab[1][2], ab[1][3]};
                    uint4 B[4] = {bb[1][0], bb[1][1], bb[1][2], bb[1][3]};
                    if (c0i + 3 < 64) {
                        #pragma unroll
                        for (int mt = 0; mt < 4; mt++) ab[1][mt] = __ldcg(ap + mt*2048 + (c0i+3)*32);
                        bb[1][0] = __ldcg(bt0 + (c0i+3)*64);  bb[1][1] = __ldcg(bt0 + (c0i+3)*64 + 32);
                        bb[1][2] = __ldcg(bt1 + (c0i+3)*64);  bb[1][3] = __ldcg(bt1 + (c0i+3)*64 + 32);
                    }
                    XGMMA(A, B);
                }
            }
            // epilogue (R10-proven): fp16 xg[t][b][u][g]
            #pragma unroll
            for (int mt = 0; mt < 4; mt++) {
                #pragma unroll
                for (int nt = 0; nt < 8; nt++) {
                    const int cbx  = cbb + (nt >> 2);
                    const int cidx = (nt & 3)*8 + q4*2;
                    const int g    = cidx >> 3;
                    const int j    = cidx & 7;
                    const int u    = cbx*8 + j;
                    const int b    = mt*16 + lq;
                    size_t base0 = (((size_t)t*NB + b)*HID + u)*4 + g;
                    g_xgh[base0]     = __float2half(xac[mt][nt][0]);
                    g_xgh[base0 + 4] = __float2half(xac[mt][nt][1]);
                    size_t base1 = base0 + (size_t)8*HID*4;
                    g_xgh[base1]     = __float2half(xac[mt][nt][2]);
                    g_xgh[base1 + 4] = __float2half(xac[mt][nt][3]);
                }
            }
            __syncwarp();
            if (lane == 0) bar_red_release(&g_xfl[t]);
        }
        return;
    }

    // ================= RECURRENCE (R9-proven, + precomputed tail) ====================
    extern __shared__ uint32_t sm[];
    uint32_t* sWh = sm;
    uint32_t* sWi = sm + WTILE;
    float*    gsm = (float*)(sm + 2*WTILE);    // 4 regions: x(0,1), h(2,3)

    const int cb   = blockIdx.x;
    const bool isx = (w < 4);
    const int wl   = w & 3;
    const int whalf = wl & 1;
    const int wkq   = wl >> 1;

    {
        const uint4* s0 = reinterpret_cast<const uint4*>(g_wt + (size_t)cb*WTILE);
        const uint4* s1 = reinterpret_cast<const uint4*>(g_wt + (size_t)(NCTA + cb)*WTILE);
        uint4* d0 = reinterpret_cast<uint4*>(sWh);
        uint4* d1 = reinterpret_cast<uint4*>(sWi);
        #pragma unroll
        for (int i = 0; i < 16; i++) d0[tid + i*256] = __ldcg(s0 + tid + i*256);
        #pragma unroll
        for (int i = 0; i < 16; i++) d1[tid + i*256] = __ldcg(s1 + tid + i*256);
    }

    const int pb = tid >> 2;
    const int p  = tid & 3;
    const int u0 = cb*8 + 2*p;
    const int gbase = pb*HID + u0;

    float2 c_r = *reinterpret_cast<const float2*>(c0 + gbase);
    float2 mh2 = *reinterpret_cast<const float2*>(mh + gbase);
    const int hwaddr = hp_addr(pb, cb*4 + p);

    float bs[2][4];
    #pragma unroll
    for (int i = 0; i < 2; i++)
        #pragma unroll
        for (int g = 0; g < 4; g++)
            bs[i][g] = b_ih[g*HID + u0 + i] + b_hh[g*HID + u0 + i];
    __syncthreads();

    const uint4* wh4 = reinterpret_cast<const uint4*>(sWh);
    const uint4* wi4 = reinterpret_cast<const uint4*>(sWi);
    const uint4* xg4 = reinterpret_cast<const uint4*>(g_xgh);
    const int xgoff = (pb << 9) + cb*4 + p;

    for (int t = 0; t < SEQ; ++t) {
        float acc[2][4][4];
        #pragma unroll
        for (int mt = 0; mt < 2; mt++)
            #pragma unroll
            for (int nt = 0; nt < 4; nt++)
                #pragma unroll
                for (int e = 0; e < 4; e++) acc[mt][nt][e] = 0.f;

        if (isx) {
            if (t < TSIN) {   // inline x contribution (R9 verbatim)
                const uint4* xb = reinterpret_cast<const uint4*>(g_xv + (size_t)t*32768);
                MMA_PASS(xb, wi4);
                STORE_GATES(wkq);              // regions 0,1
            }
        } else {
            if (t > 0) {
                if (lane == 0) {
                    while (bar_ld_acquire(&g_bar[t-1]) < NCTA) { }
                }
                __syncwarp();
            }
            const uint4* hb = reinterpret_cast<const uint4*>(g_hm[t & 1]);
            MMA_PASS(hb, wh4);
            STORE_GATES(2 + wkq);              // regions 2,3
        }

        // tail steps: ensure helper xg[t] is complete before cell reads it
        if (t >= TSIN && tid == 0) {
            while (bar_ld_acquire(&g_xfl[t]) < 64) { }
        }
        __syncthreads();

        // fused LSTM cell
        uint32_t* hmn = g_hm[(t + 1) & 1];
        float xr[2][4];
        if (t >= TSIN) {
            uint4 q = __ldcg(xg4 + (size_t)t*(NB*512) + xgoff);
            const __half* hq = reinterpret_cast<const __half*>(&q);
            #pragma unroll
            for (int g = 0; g < 4; g++) {
                xr[0][g] = __half2float(hq[g]);
                xr[1][g] = __half2float(hq[4 + g]);
            }
        }
        float hnv[2], cnv[2];
        #pragma unroll
        for (int i = 0; i < 2; i++) {
            const int j = 2*p + i;
            float gt[4];
            #pragma unroll
            for (int g = 0; g < 4; g++) {
                const int c = g*8 + j;
                float xpart = (t < TSIN)
                    ? (gsm[0*GSZ + pb*GST + c] + gsm[1*GSZ + pb*GST + c])
                    : xr[i][g];
                gt[g] = xpart + gsm[2*GSZ + pb*GST + c] + gsm[3*GSZ + pb*GST + c]
                      + bs[i][g];
            }
            float ig = sigf(gt[0]);
            float fg = sigf(gt[1]);
            float gv = tanh_f(gt[2]);
            float og = sigf(gt[3]);
            float cp = (i == 0) ? c_r.x : c_r.y;
            float cn = fg*cp + ig*gv;
            cnv[i] = cn;
            hnv[i] = og*tanh_f(cn);
        }
        c_r.x = cnv[0]; c_r.y = cnv[1];

        // publish h[t+1] first, release, then private gmem work in the shadow (R11-proven)
        hmn[hwaddr] = packh2(hnv[0]*mh2.x, hnv[1]*mh2.y);
        if (t < SEQ - 1) {
            __syncthreads();
            if (tid == 0) bar_red_release(&g_bar[t]);
        }

        *reinterpret_cast<float2*>(out + (size_t)t*(NB*HID) + gbase)
            = make_float2(hnv[0], hnv[1]);
        if (t == SEQ - 1) {
            *reinterpret_cast<float2*>(out + SBH + gbase)          = make_float2(hnv[0], hnv[1]);
            *reinterpret_cast<float2*>(out + SBH + NB*HID + gbase) = make_float2(cnv[0], cnv[1]);
        }
    }
}

extern "C" void kernel_launch(void* const* d_in, const int* in_sizes, int n_in,
                              void* d_out, int out_size) {
    const float* x      = (const float*)d_in[0];
    const float* h0     = (const float*)d_in[1];
    const float* c0     = (const float*)d_in[2];
    const float* mask_x = (const float*)d_in[3];
    const float* mask_h = (const float*)d_in[4];
    const float* W_ih   = (const float*)d_in[5];
    const float* W_hh   = (const float*)d_in[6];
    const float* b_ih   = (const float*)d_in[7];
    const float* b_hh   = (const float*)d_in[8];
    float* out = (float*)d_out;

    const int smem_rnn = (2*WTILE + 4*GSZ) * 4;   // 164,864 B
    cudaFuncSetAttribute(k_main, cudaFuncAttributeMaxDynamicSharedMemorySize, smem_rnn);

    k_xprep<<<(SEQ*NB*HID/2)/256, 256>>>(x, mask_x);
    k_setup<<<(NB*HID/2)/256, 256>>>(h0, mask_h);
    k_wprep<<<(NCTA*WTILE)/256, 256>>>(W_hh, 0);
    k_wprep<<<(NCTA*WTILE)/256, 256>>>(W_ih, 1);
    k_main<<<NCTA + NHELP, 256, smem_rnn>>>(c0, mask_h, b_ih, b_hh, out);
    (void)in_sizes; (void)n_in; (void)out_size;
}